// round 6
// baseline (speedup 1.0000x reference)
#include <cuda_runtime.h>

#define T_STEPS 1000
#define B_TOT   256
#define FIN     39
#define H       100
#define G3      300
#define NCLS    20
#define GSTR    (B_TOT * G3)

typedef unsigned long long u64;

// 307 MB scratch for precomputed input gates gi[t][b][g]
// (includes b_ih for all gates, plus b_hh for r,z gates)
__device__ float g_gi[(size_t)T_STEPS * B_TOT * G3];

__device__ __forceinline__ u64 pk(float x, float y) {
    u64 r; asm("mov.b64 %0,{%1,%2};" : "=l"(r) : "f"(x), "f"(y)); return r;
}
__device__ __forceinline__ void fma2(u64 &d, u64 a, u64 b) {
    asm("fma.rn.f32x2 %0,%1,%2,%0;" : "+l"(d) : "l"(a), "l"(b));
}
__device__ __forceinline__ float hsum2(u64 a) {
    float x, y; asm("mov.b64 {%0,%1},%2;" : "=f"(x), "=f"(y) : "l"(a)); return x + y;
}
__device__ __forceinline__ void lds_v2u64(u64 &a, u64 &b, unsigned addr) {
    asm volatile("ld.shared.v2.u64 {%0,%1},[%2];" : "=l"(a), "=l"(b) : "r"(addr));
}
__device__ __forceinline__ void lds_u64(u64 &a, unsigned addr) {
    asm volatile("ld.shared.u64 %0,[%1];" : "=l"(a) : "r"(addr));
}
__device__ __forceinline__ float sigf(float x) {
    return __fdividef(1.0f, 1.0f + __expf(-x));
}
__device__ __forceinline__ float tanh_acc(float x) {
    return 2.0f * sigf(2.0f * x) - 1.0f;
}

// ---------------------------------------------------------------------------
// Kernel 1: gi[t][b][g] = bias[g] + sum_k x[t][b][k] * W_ih[g][k]
// bias folds b_ih (all gates) + b_hh (r,z gates only — n's b_hh sits inside r*()).
// ---------------------------------------------------------------------------
#define K1_PAIRS 64
#define K1_TILE  32

__global__ void __launch_bounds__(320, 2) gi_precompute_kernel(
    const float* __restrict__ mfcc0, const float* __restrict__ mfcc1,
    const float* __restrict__ mfcc2,
    const float* __restrict__ W_ih, const float* __restrict__ b_ih,
    const float* __restrict__ b_hh)
{
    __shared__ __align__(16) float xt[2][K1_TILE][40];
    const int tid = threadIdx.x;
    const int g = (tid < G3) ? tid : (G3 - 1);

    u64 wih[20];
    {
        const float* w = W_ih + g * FIN;
        #pragma unroll
        for (int j = 0; j < 19; j++) wih[j] = pk(w[2 * j], w[2 * j + 1]);
        wih[19] = pk(w[38], 0.0f);
    }
    const float bias = b_ih[g] + ((g < 2 * H) ? b_hh[g] : 0.0f);
    const int p0 = blockIdx.x * K1_PAIRS;

    int fpair[4], fk[4];
    const float* fptr[4];
    bool fok[4];
    #pragma unroll
    for (int s = 0; s < 4; s++) {
        int idx = tid + s * 320;
        int pr = idx / 40, k = idx - pr * 40;
        fpair[s] = pr; fk[s] = k;
        fok[s] = (k < 39);
        const float* src = (k < 13) ? mfcc0 : (k < 26) ? mfcc1 : mfcc2;
        int f = (k < 13) ? k : (k < 26) ? (k - 13) : (k - 26);
        fptr[s] = src + (size_t)(p0 + pr) * 13 + f;
    }

    #pragma unroll
    for (int s = 0; s < 4; s++)
        xt[0][fpair[s]][fk[s]] = fok[s] ? __ldg(fptr[s]) : 0.0f;
    __syncthreads();

    const unsigned xB0 = (unsigned)__cvta_generic_to_shared(&xt[0][0][0]);

    for (int tile = 0; tile < K1_PAIRS / K1_TILE; tile++) {
        if (tile + 1 < K1_PAIRS / K1_TILE) {
            #pragma unroll
            for (int s = 0; s < 4; s++) {
                fptr[s] += K1_TILE * 13;
                xt[(tile + 1) & 1][fpair[s]][fk[s]] = fok[s] ? __ldg(fptr[s]) : 0.0f;
            }
        }
        const unsigned xB = xB0 + (tile & 1) * (K1_TILE * 40 * 4);
        const int pb = p0 + tile * K1_TILE;
        #pragma unroll 2
        for (int pair = 0; pair < K1_TILE; pair += 2) {
            u64 a0 = 0, a1 = 0, c0 = 0, c1 = 0;
            unsigned ad = xB + pair * 160;
            #pragma unroll
            for (int j = 0; j < 10; j++) {
                u64 p, q, p2, q2;
                lds_v2u64(p,  q,  ad + j * 16);
                lds_v2u64(p2, q2, ad + 160 + j * 16);
                fma2(a0, wih[2 * j],     p);
                fma2(a1, wih[2 * j + 1], q);
                fma2(c0, wih[2 * j],     p2);
                fma2(c1, wih[2 * j + 1], q2);
            }
            if (tid < G3) {
                g_gi[(size_t)(pb + pair) * G3 + g]     = hsum2(a0) + hsum2(a1) + bias;
                g_gi[(size_t)(pb + pair + 1) * G3 + g] = hsum2(c0) + hsum2(c1) + bias;
            }
        }
        __syncthreads();
    }
}

// ---------------------------------------------------------------------------
// Kernel 2: persistent recurrent GRU. 128 CTAs x 800 threads (25 warps).
// thread = (h = tid>>3, c = tid&7). Thread computes r,z,n partials for its h
// over K-chunk [c*14, c*14+14), both batches (42 fma2/step).
// SMEM h layout: chunk c lives in a 16-float (64B) slot -> all v2.u64 loads
// 16B-aligned; slots' last 2 floats are permanent zeros.
// Octet reduction: role-aware butterfly (8 SHFL total incl. z-ship).
// Lanes c<2 finalize r/tanh/h-update (batch = c); lanes 2,3 compute z-sigmoid
// in parallel and ship it via bfly(2). h double-buffered -> 1 barrier/step.
// ---------------------------------------------------------------------------
#define CH     14          // used floats per chunk
#define SLOT   64          // chunk slot bytes (16 floats)
#define HPB    512         // bytes per batch (8 slots)
#define BUFB   1024        // bytes per buffer (2 batches)

__global__ void __launch_bounds__(800, 1) gru_rec_kernel(
    const float* __restrict__ len0,
    const float* __restrict__ W_hh, const float* __restrict__ b_hh,
    const float* __restrict__ W_out, const float* __restrict__ b_out,
    float* __restrict__ out)
{
    __shared__ __align__(16) float h_sh[2 * BUFB / 4];   // 2 bufs x 1024B
    __shared__ float feat_sh[2][2 * H];

    const int tid = threadIdx.x;
    const int h   = tid >> 3;          // 0..99
    const int c   = tid & 7;           // K-chunk; roles: c<2 r/n (b=c), c=2,3 z (b=c-2)
    const int b0  = blockIdx.x * 2;
    const int bl  = c & 1;             // this lane's batch for role work

    // zero both h buffers (incl pad floats)
    for (int i = tid; i < 2 * BUFB / 4; i += 800) h_sh[i] = 0.0f;

    // persistent W_hh chunk rows for 3 gates, zero-padded beyond k=100
    const int k0 = c * CH;
    u64 w[3][7];
    #pragma unroll
    for (int i = 0; i < 3; i++) {
        const float* wr = W_hh + (h + i * H) * H;
        #pragma unroll
        for (int j = 0; j < 7; j++) {
            int k = k0 + 2 * j;
            float x0 = (k     < H) ? wr[k]     : 0.0f;
            float x1 = (k + 1 < H) ? wr[k + 1] : 0.0f;
            w[i][j] = pk(x0, x1);
        }
    }

    // gi pointer: c<2 -> &gi[b][h] (reads +0 for r, +200 for n)
    //             c=2,3 -> &gi[b][H+h] (reads +0 for z)
    const float* gp = g_gi;
    float bh2 = 0.0f;
    if (c < 2) {
        gp = g_gi + (size_t)(b0 + bl) * G3 + h;
        bh2 = b_hh[2 * H + h];
    } else if (c < 4) {
        gp = g_gi + (size_t)(b0 + bl) * G3 + H + h;
    }

    // current gi values
    float gA = 0.0f, gB = 0.0f;        // gA: r (c<2) or z (c=2,3); gB: n (c<2)
    if (c < 4) {
        gA = __ldg(gp);
        if (c < 2) gB = __ldg(gp + 2 * H);
    }

    float hprev = 0.0f, hs = 0.0f, hm = -1e30f;

    const unsigned base = (unsigned)__cvta_generic_to_shared(&h_sh[0]);
    unsigned cur = base, nxt = base + BUFB;        // explicit double-buffer swap
    const unsigned adc = (unsigned)(c * SLOT);     // this lane's chunk slot
    // h-writer slot address components (lanes c<2)
    const unsigned woff = (unsigned)((h / CH) * SLOT + (h % CH) * 4 + bl * HPB);

    __syncthreads();

    for (int t = 0; t < T_STEPS; t++) {
        // prefetch gi(t+1)
        float pA = 0.0f, pB = 0.0f;
        if (t + 1 < T_STEPS && c < 4) {
            const float* gq = gp + GSTR;
            pA = __ldg(gq);
            if (c < 2) pB = __ldg(gq + 2 * H);
            gp = gq;
        }

        // partial dots: 3 gates x 2 batches
        u64 ar0 = 0, az0 = 0, an0 = 0, ar1 = 0, az1 = 0, an1 = 0;
        {
            const unsigned a0 = cur + adc;          // batch 0 chunk slot
            u64 q0, q1, q2, q3, q4, q5, q6;
            lds_v2u64(q0, q1, a0);      lds_v2u64(q2, q3, a0 + 16);
            lds_v2u64(q4, q5, a0 + 32); lds_u64(q6, a0 + 48);
            fma2(ar0, w[0][0], q0); fma2(az0, w[1][0], q0); fma2(an0, w[2][0], q0);
            fma2(ar0, w[0][1], q1); fma2(az0, w[1][1], q1); fma2(an0, w[2][1], q1);
            fma2(ar0, w[0][2], q2); fma2(az0, w[1][2], q2); fma2(an0, w[2][2], q2);
            fma2(ar0, w[0][3], q3); fma2(az0, w[1][3], q3); fma2(an0, w[2][3], q3);
            fma2(ar0, w[0][4], q4); fma2(az0, w[1][4], q4); fma2(an0, w[2][4], q4);
            fma2(ar0, w[0][5], q5); fma2(az0, w[1][5], q5); fma2(an0, w[2][5], q5);
            fma2(ar0, w[0][6], q6); fma2(az0, w[1][6], q6); fma2(an0, w[2][6], q6);
        }
        {
            const unsigned a1 = cur + adc + HPB;    // batch 1 chunk slot
            u64 r0, r1, r2, r3, r4, r5, r6;
            lds_v2u64(r0, r1, a1);      lds_v2u64(r2, r3, a1 + 16);
            lds_v2u64(r4, r5, a1 + 32); lds_u64(r6, a1 + 48);
            fma2(ar1, w[0][0], r0); fma2(az1, w[1][0], r0); fma2(an1, w[2][0], r0);
            fma2(ar1, w[0][1], r1); fma2(az1, w[1][1], r1); fma2(an1, w[2][1], r1);
            fma2(ar1, w[0][2], r2); fma2(az1, w[1][2], r2); fma2(an1, w[2][2], r2);
            fma2(ar1, w[0][3], r3); fma2(az1, w[1][3], r3); fma2(an1, w[2][3], r3);
            fma2(ar1, w[0][4], r4); fma2(az1, w[1][4], r4); fma2(an1, w[2][4], r4);
            fma2(ar1, w[0][5], r5); fma2(az1, w[1][5], r5); fma2(an1, w[2][5], r5);
            fma2(ar1, w[0][6], r6); fma2(az1, w[1][6], r6); fma2(an1, w[2][6], r6);
        }

        float r0s = hsum2(ar0), z0s = hsum2(az0), n0s = hsum2(an0);
        float r1s = hsum2(ar1), z1s = hsum2(az1), n1s = hsum2(an1);

        // ---- role-aware octet butterfly (8 SHFL incl z-ship) ----
        // Round 1 (xor 1): keep own batch bl, receive partner's partial of bl
        float rr = bl ? r1s : r0s;
        float zz = bl ? z1s : z0s;
        float nn = bl ? n1s : n0s;
        rr += __shfl_xor_sync(0xFFFFFFFFu, bl ? r0s : r1s, 1);
        zz += __shfl_xor_sync(0xFFFFFFFFu, bl ? z0s : z1s, 1);
        nn += __shfl_xor_sync(0xFFFFFFFFu, bl ? n0s : n1s, 1);
        // Round 2 (xor 2): lanes c&2 own z (send r), others own r/n (send z)
        {
            float g2 = __shfl_xor_sync(0xFFFFFFFFu, (c & 2) ? rr : zz, 2);
            if (c & 2) zz += g2; else rr += g2;
            nn += __shfl_xor_sync(0xFFFFFFFFu, nn, 2);   // valid on c&2==0 lanes
        }
        // Round 3 (xor 4): same role split
        {
            float g3 = __shfl_xor_sync(0xFFFFFFFFu, (c & 2) ? zz : rr, 4);
            if (c & 2) zz += g3; else rr += g3;
            nn += __shfl_xor_sync(0xFFFFFFFFu, nn, 4);
        }
        // lanes 0,1: rr = Sr, nn = Sn (own batch); lanes 2,3: zz = Sz (own batch)

        // parallel sigmoid: r on lanes 0,1; z on lanes 2,3
        float sig = sigf(gA + ((c & 2) ? zz : rr));
        float zx = __shfl_xor_sync(0xFFFFFFFFu, sig, 2);  // lane bl <- z from lane 2+bl

        if (c < 2) {
            float n  = tanh_acc(gB + sig * (nn + bh2));
            float hn = n + zx * (hprev - n);
            hprev = hn;
            hs += hn;
            hm = fmaxf(hm, hn);
            // store to NEXT buffer
            asm volatile("st.shared.f32 [%0], %1;" :: "r"(nxt + woff), "f"(hprev));
        }
        gA = pA; gB = pB;
        { unsigned tmp = cur; cur = nxt; nxt = tmp; }
        __syncthreads();
    }

    // pooling features
    if (c < 2) {
        float inv = 1.0f / len0[b0 + bl];
        feat_sh[bl][h]     = hs * inv;
        feat_sh[bl][H + h] = hm;
    }
    __syncthreads();

    // output linear: [2 x 20] = feat[2 x 200] @ W_out^T + b_out
    if (tid < 2 * NCLS) {
        int bb = tid / NCLS, cc = tid % NCLS;
        const float* wr = W_out + cc * 2 * H;
        float acc = b_out[cc];
        #pragma unroll 4
        for (int j = 0; j < 2 * H; j++) acc += feat_sh[bb][j] * wr[j];
        out[(b0 + bb) * NCLS + cc] = acc;
    }
}

extern "C" void kernel_launch(void* const* d_in, const int* in_sizes, int n_in,
                              void* d_out, int out_size)
{
    const float* mfcc0 = (const float*)d_in[0];
    const float* mfcc1 = (const float*)d_in[1];
    const float* mfcc2 = (const float*)d_in[2];
    const float* len0  = (const float*)d_in[3];
    const float* W_ih  = (const float*)d_in[4];
    const float* W_hh  = (const float*)d_in[5];
    const float* b_ih  = (const float*)d_in[6];
    const float* b_hh  = (const float*)d_in[7];
    const float* W_out = (const float*)d_in[8];
    const float* b_out = (const float*)d_in[9];
    float* out = (float*)d_out;

    gi_precompute_kernel<<<(T_STEPS * B_TOT) / K1_PAIRS, 320>>>(
        mfcc0, mfcc1, mfcc2, W_ih, b_ih, b_hh);
    gru_rec_kernel<<<B_TOT / 2, 800>>>(len0, W_hh, b_hh, W_out, b_out, out);
}

// round 7
// speedup vs baseline: 1.6703x; 1.6703x over previous
#include <cuda_runtime.h>

#define T_STEPS 1000
#define B_TOT   256
#define FIN     39
#define H       100
#define G3      300
#define NCLS    20
#define GSTR    (B_TOT * G3)

typedef unsigned long long u64;

// 307 MB scratch for precomputed input gates gi[t][b][g]
// (includes b_ih for all gates, plus b_hh for r,z gates)
__device__ float g_gi[(size_t)T_STEPS * B_TOT * G3];

__device__ __forceinline__ u64 pk(float x, float y) {
    u64 r; asm("mov.b64 %0,{%1,%2};" : "=l"(r) : "f"(x), "f"(y)); return r;
}
__device__ __forceinline__ void fma2(u64 &d, u64 a, u64 b) {
    asm("fma.rn.f32x2 %0,%1,%2,%0;" : "+l"(d) : "l"(a), "l"(b));
}
__device__ __forceinline__ float hsum2(u64 a) {
    float x, y; asm("mov.b64 {%0,%1},%2;" : "=f"(x), "=f"(y) : "l"(a)); return x + y;
}
__device__ __forceinline__ void lds_v2u64(u64 &a, u64 &b, unsigned addr) {
    asm volatile("ld.shared.v2.u64 {%0,%1},[%2];" : "=l"(a), "=l"(b) : "r"(addr));
}
__device__ __forceinline__ void lds_u64(u64 &a, unsigned addr) {
    asm volatile("ld.shared.u64 %0,[%1];" : "=l"(a) : "r"(addr));
}
__device__ __forceinline__ float sigf(float x) {
    return __fdividef(1.0f, 1.0f + __expf(-x));
}
__device__ __forceinline__ float tanh_acc(float x) {
    return 2.0f * sigf(2.0f * x) - 1.0f;
}

// ---------------------------------------------------------------------------
// Kernel 1: gi[t][b][g] = bias[g] + sum_k x[t][b][k] * W_ih[g][k]
// bias folds b_ih (all gates) + b_hh (r,z gates only — n's b_hh sits inside r*()).
// ---------------------------------------------------------------------------
#define K1_PAIRS 64
#define K1_TILE  32

__global__ void __launch_bounds__(320, 2) gi_precompute_kernel(
    const float* __restrict__ mfcc0, const float* __restrict__ mfcc1,
    const float* __restrict__ mfcc2,
    const float* __restrict__ W_ih, const float* __restrict__ b_ih,
    const float* __restrict__ b_hh)
{
    __shared__ __align__(16) float xt[2][K1_TILE][40];
    const int tid = threadIdx.x;
    const int g = (tid < G3) ? tid : (G3 - 1);

    u64 wih[20];
    {
        const float* w = W_ih + g * FIN;
        #pragma unroll
        for (int j = 0; j < 19; j++) wih[j] = pk(w[2 * j], w[2 * j + 1]);
        wih[19] = pk(w[38], 0.0f);
    }
    const float bias = b_ih[g] + ((g < 2 * H) ? b_hh[g] : 0.0f);
    const int p0 = blockIdx.x * K1_PAIRS;

    int fpair[4], fk[4];
    const float* fptr[4];
    bool fok[4];
    #pragma unroll
    for (int s = 0; s < 4; s++) {
        int idx = tid + s * 320;
        int pr = idx / 40, k = idx - pr * 40;
        fpair[s] = pr; fk[s] = k;
        fok[s] = (k < 39);
        const float* src = (k < 13) ? mfcc0 : (k < 26) ? mfcc1 : mfcc2;
        int f = (k < 13) ? k : (k < 26) ? (k - 13) : (k - 26);
        fptr[s] = src + (size_t)(p0 + pr) * 13 + f;
    }

    #pragma unroll
    for (int s = 0; s < 4; s++)
        xt[0][fpair[s]][fk[s]] = fok[s] ? __ldg(fptr[s]) : 0.0f;
    __syncthreads();

    const unsigned xB0 = (unsigned)__cvta_generic_to_shared(&xt[0][0][0]);

    for (int tile = 0; tile < K1_PAIRS / K1_TILE; tile++) {
        if (tile + 1 < K1_PAIRS / K1_TILE) {
            #pragma unroll
            for (int s = 0; s < 4; s++) {
                fptr[s] += K1_TILE * 13;
                xt[(tile + 1) & 1][fpair[s]][fk[s]] = fok[s] ? __ldg(fptr[s]) : 0.0f;
            }
        }
        const unsigned xB = xB0 + (tile & 1) * (K1_TILE * 40 * 4);
        const int pb = p0 + tile * K1_TILE;
        #pragma unroll 2
        for (int pair = 0; pair < K1_TILE; pair += 2) {
            u64 a0 = 0, a1 = 0, c0 = 0, c1 = 0;
            unsigned ad = xB + pair * 160;
            #pragma unroll
            for (int j = 0; j < 10; j++) {
                u64 p, q, p2, q2;
                lds_v2u64(p,  q,  ad + j * 16);
                lds_v2u64(p2, q2, ad + 160 + j * 16);
                fma2(a0, wih[2 * j],     p);
                fma2(a1, wih[2 * j + 1], q);
                fma2(c0, wih[2 * j],     p2);
                fma2(c1, wih[2 * j + 1], q2);
            }
            if (tid < G3) {
                g_gi[(size_t)(pb + pair) * G3 + g]     = hsum2(a0) + hsum2(a1) + bias;
                g_gi[(size_t)(pb + pair + 1) * G3 + g] = hsum2(c0) + hsum2(c1) + bias;
            }
        }
        __syncthreads();
    }
}

// ---------------------------------------------------------------------------
// Kernel 2: persistent recurrent GRU. 128 CTAs x 800 threads (25 warps).
// thread = (h = tid>>3, c = tid&7). Thread computes r,z,n partials for its h
// over K-chunk [c*14, c*14+14), both batches (42 fma2/step).
// SMEM h layout: chunk c in an 80B slot (20 floats): 16B-aligned AND
// bank-conflict-free (base banks (c*20)%32 = {0,20,8,28,16,4,24,12}).
// Same-c lanes across octets read identical addresses -> broadcast.
// Octet reduction: role-aware butterfly (8 SHFL total incl. z-ship).
// Lanes c<2 finalize r/tanh/h-update (batch = c); lanes 2,3 compute z-sigmoid
// in parallel and ship it via bfly(2). h double-buffered -> 1 barrier/step.
// ---------------------------------------------------------------------------
#define CH     14          // used floats per chunk
#define SLOT   80          // chunk slot bytes (20 floats)
#define HPB    640         // bytes per batch (8 slots)
#define BUFB   1280        // bytes per buffer (2 batches)

__global__ void __launch_bounds__(800, 1) gru_rec_kernel(
    const float* __restrict__ len0,
    const float* __restrict__ W_hh, const float* __restrict__ b_hh,
    const float* __restrict__ W_out, const float* __restrict__ b_out,
    float* __restrict__ out)
{
    __shared__ __align__(16) float h_sh[2 * BUFB / 4];   // 2 bufs x 1280B
    __shared__ float feat_sh[2][2 * H];

    const int tid = threadIdx.x;
    const int h   = tid >> 3;          // 0..99
    const int c   = tid & 7;           // K-chunk; roles: c<2 r/n (b=c), c=2,3 z (b=c-2)
    const int b0  = blockIdx.x * 2;
    const int bl  = c & 1;             // this lane's batch for role work

    // zero both h buffers (incl pad floats — pads never written again)
    for (int i = tid; i < 2 * BUFB / 4; i += 800) h_sh[i] = 0.0f;

    // persistent W_hh chunk rows for 3 gates, zero-padded beyond k=100
    const int k0 = c * CH;
    u64 w[3][7];
    #pragma unroll
    for (int i = 0; i < 3; i++) {
        const float* wr = W_hh + (h + i * H) * H;
        #pragma unroll
        for (int j = 0; j < 7; j++) {
            int k = k0 + 2 * j;
            float x0 = (k     < H) ? wr[k]     : 0.0f;
            float x1 = (k + 1 < H) ? wr[k + 1] : 0.0f;
            w[i][j] = pk(x0, x1);
        }
    }

    // gi pointer: c<2 -> &gi[b][h] (reads +0 for r, +200 for n)
    //             c=2,3 -> &gi[b][H+h] (reads +0 for z)
    const float* gp = g_gi;
    float bh2 = 0.0f;
    if (c < 2) {
        gp = g_gi + (size_t)(b0 + bl) * G3 + h;
        bh2 = b_hh[2 * H + h];
    } else if (c < 4) {
        gp = g_gi + (size_t)(b0 + bl) * G3 + H + h;
    }

    // current gi values
    float gA = 0.0f, gB = 0.0f;        // gA: r (c<2) or z (c=2,3); gB: n (c<2)
    if (c < 4) {
        gA = __ldg(gp);
        if (c < 2) gB = __ldg(gp + 2 * H);
    }

    float hprev = 0.0f, hs = 0.0f, hm = -1e30f;

    const unsigned base = (unsigned)__cvta_generic_to_shared(&h_sh[0]);
    unsigned cur = base, nxt = base + BUFB;        // explicit double-buffer swap
    const unsigned adc = (unsigned)(c * SLOT);     // this lane's chunk slot
    // h-writer slot address components (lanes c<2)
    const unsigned woff = (unsigned)((h / CH) * SLOT + (h % CH) * 4 + bl * HPB);

    __syncthreads();

    for (int t = 0; t < T_STEPS; t++) {
        // prefetch gi(t+1)
        float pA = 0.0f, pB = 0.0f;
        if (t + 1 < T_STEPS && c < 4) {
            const float* gq = gp + GSTR;
            pA = __ldg(gq);
            if (c < 2) pB = __ldg(gq + 2 * H);
            gp = gq;
        }

        // partial dots: 3 gates x 2 batches
        u64 ar0 = 0, az0 = 0, an0 = 0, ar1 = 0, az1 = 0, an1 = 0;
        {
            const unsigned a0 = cur + adc;          // batch 0 chunk slot
            u64 q0, q1, q2, q3, q4, q5, q6;
            lds_v2u64(q0, q1, a0);      lds_v2u64(q2, q3, a0 + 16);
            lds_v2u64(q4, q5, a0 + 32); lds_u64(q6, a0 + 48);
            fma2(ar0, w[0][0], q0); fma2(az0, w[1][0], q0); fma2(an0, w[2][0], q0);
            fma2(ar0, w[0][1], q1); fma2(az0, w[1][1], q1); fma2(an0, w[2][1], q1);
            fma2(ar0, w[0][2], q2); fma2(az0, w[1][2], q2); fma2(an0, w[2][2], q2);
            fma2(ar0, w[0][3], q3); fma2(az0, w[1][3], q3); fma2(an0, w[2][3], q3);
            fma2(ar0, w[0][4], q4); fma2(az0, w[1][4], q4); fma2(an0, w[2][4], q4);
            fma2(ar0, w[0][5], q5); fma2(az0, w[1][5], q5); fma2(an0, w[2][5], q5);
            fma2(ar0, w[0][6], q6); fma2(az0, w[1][6], q6); fma2(an0, w[2][6], q6);
        }
        {
            const unsigned a1 = cur + adc + HPB;    // batch 1 chunk slot
            u64 r0, r1, r2, r3, r4, r5, r6;
            lds_v2u64(r0, r1, a1);      lds_v2u64(r2, r3, a1 + 16);
            lds_v2u64(r4, r5, a1 + 32); lds_u64(r6, a1 + 48);
            fma2(ar1, w[0][0], r0); fma2(az1, w[1][0], r0); fma2(an1, w[2][0], r0);
            fma2(ar1, w[0][1], r1); fma2(az1, w[1][1], r1); fma2(an1, w[2][1], r1);
            fma2(ar1, w[0][2], r2); fma2(az1, w[1][2], r2); fma2(an1, w[2][2], r2);
            fma2(ar1, w[0][3], r3); fma2(az1, w[1][3], r3); fma2(an1, w[2][3], r3);
            fma2(ar1, w[0][4], r4); fma2(az1, w[1][4], r4); fma2(an1, w[2][4], r4);
            fma2(ar1, w[0][5], r5); fma2(az1, w[1][5], r5); fma2(an1, w[2][5], r5);
            fma2(ar1, w[0][6], r6); fma2(az1, w[1][6], r6); fma2(an1, w[2][6], r6);
        }

        float r0s = hsum2(ar0), z0s = hsum2(az0), n0s = hsum2(an0);
        float r1s = hsum2(ar1), z1s = hsum2(az1), n1s = hsum2(an1);

        // ---- role-aware octet butterfly (8 SHFL incl z-ship) ----
        // Round 1 (xor 1): keep own batch bl, receive partner's partial of bl
        float rr = bl ? r1s : r0s;
        float zz = bl ? z1s : z0s;
        float nn = bl ? n1s : n0s;
        rr += __shfl_xor_sync(0xFFFFFFFFu, bl ? r0s : r1s, 1);
        zz += __shfl_xor_sync(0xFFFFFFFFu, bl ? z0s : z1s, 1);
        nn += __shfl_xor_sync(0xFFFFFFFFu, bl ? n0s : n1s, 1);
        // Round 2 (xor 2): lanes c&2 own z (send r), others own r/n (send z)
        {
            float g2 = __shfl_xor_sync(0xFFFFFFFFu, (c & 2) ? rr : zz, 2);
            if (c & 2) zz += g2; else rr += g2;
            nn += __shfl_xor_sync(0xFFFFFFFFu, nn, 2);   // valid on c&2==0 lanes
        }
        // Round 3 (xor 4): same role split
        {
            float g3 = __shfl_xor_sync(0xFFFFFFFFu, (c & 2) ? zz : rr, 4);
            if (c & 2) zz += g3; else rr += g3;
            nn += __shfl_xor_sync(0xFFFFFFFFu, nn, 4);
        }
        // lanes 0,1: rr = Sr, nn = Sn (own batch); lanes 2,3: zz = Sz (own batch)

        // parallel sigmoid: r on lanes 0,1; z on lanes 2,3
        float sig = sigf(gA + ((c & 2) ? zz : rr));
        float zx = __shfl_xor_sync(0xFFFFFFFFu, sig, 2);  // lane bl <- z from lane 2+bl

        if (c < 2) {
            float n  = tanh_acc(gB + sig * (nn + bh2));
            float hn = n + zx * (hprev - n);
            hprev = hn;
            hs += hn;
            hm = fmaxf(hm, hn);
            // store to NEXT buffer
            asm volatile("st.shared.f32 [%0], %1;" :: "r"(nxt + woff), "f"(hprev));
        }
        gA = pA; gB = pB;
        { unsigned tmp = cur; cur = nxt; nxt = tmp; }
        __syncthreads();
    }

    // pooling features
    if (c < 2) {
        float inv = 1.0f / len0[b0 + bl];
        feat_sh[bl][h]     = hs * inv;
        feat_sh[bl][H + h] = hm;
    }
    __syncthreads();

    // output linear: [2 x 20] = feat[2 x 200] @ W_out^T + b_out
    if (tid < 2 * NCLS) {
        int bb = tid / NCLS, cc = tid % NCLS;
        const float* wr = W_out + cc * 2 * H;
        float acc = b_out[cc];
        #pragma unroll 4
        for (int j = 0; j < 2 * H; j++) acc += feat_sh[bb][j] * wr[j];
        out[(b0 + bb) * NCLS + cc] = acc;
    }
}

extern "C" void kernel_launch(void* const* d_in, const int* in_sizes, int n_in,
                              void* d_out, int out_size)
{
    const float* mfcc0 = (const float*)d_in[0];
    const float* mfcc1 = (const float*)d_in[1];
    const float* mfcc2 = (const float*)d_in[2];
    const float* len0  = (const float*)d_in[3];
    const float* W_ih  = (const float*)d_in[4];
    const float* W_hh  = (const float*)d_in[5];
    const float* b_ih  = (const float*)d_in[6];
    const float* b_hh  = (const float*)d_in[7];
    const float* W_out = (const float*)d_in[8];
    const float* b_out = (const float*)d_in[9];
    float* out = (float*)d_out;

    gi_precompute_kernel<<<(T_STEPS * B_TOT) / K1_PAIRS, 320>>>(
        mfcc0, mfcc1, mfcc2, W_ih, b_ih, b_hh);
    gru_rec_kernel<<<B_TOT / 2, 800>>>(len0, W_hh, b_hh, W_out, b_out, out);
}

// round 8
// speedup vs baseline: 1.6720x; 1.0011x over previous
#include <cuda_runtime.h>

#define T_STEPS 1000
#define B_TOT   256
#define FIN     39
#define H       100
#define G3      300
#define NCLS    20
#define GSTR    (B_TOT * G3)

typedef unsigned long long u64;

// 307 MB scratch for precomputed input gates gi[t][b][g]
// (includes b_ih for all gates, plus b_hh for r,z gates)
__device__ float g_gi[(size_t)T_STEPS * B_TOT * G3];

__device__ __forceinline__ u64 pk(float x, float y) {
    u64 r; asm("mov.b64 %0,{%1,%2};" : "=l"(r) : "f"(x), "f"(y)); return r;
}
__device__ __forceinline__ void fma2(u64 &d, u64 a, u64 b) {
    asm("fma.rn.f32x2 %0,%1,%2,%0;" : "+l"(d) : "l"(a), "l"(b));
}
__device__ __forceinline__ float hsum2(u64 a) {
    float x, y; asm("mov.b64 {%0,%1},%2;" : "=f"(x), "=f"(y) : "l"(a)); return x + y;
}
__device__ __forceinline__ void lds_v2u64(u64 &a, u64 &b, unsigned addr) {
    asm volatile("ld.shared.v2.u64 {%0,%1},[%2];" : "=l"(a), "=l"(b) : "r"(addr));
}
__device__ __forceinline__ void lds_u64(u64 &a, unsigned addr) {
    asm volatile("ld.shared.u64 %0,[%1];" : "=l"(a) : "r"(addr));
}
__device__ __forceinline__ float sigf(float x) {
    return __fdividef(1.0f, 1.0f + __expf(-x));
}
__device__ __forceinline__ float tanh_acc(float x) {
    return 2.0f * sigf(2.0f * x) - 1.0f;
}

// ---------------------------------------------------------------------------
// Kernel 1: gi[t][b][g] = bias[g] + sum_k x[t][b][k] * W_ih[g][k]
// bias folds b_ih (all gates) + b_hh (r,z gates only — n's b_hh sits inside r*()).
// ---------------------------------------------------------------------------
#define K1_PAIRS 64
#define K1_TILE  32

__global__ void __launch_bounds__(320, 2) gi_precompute_kernel(
    const float* __restrict__ mfcc0, const float* __restrict__ mfcc1,
    const float* __restrict__ mfcc2,
    const float* __restrict__ W_ih, const float* __restrict__ b_ih,
    const float* __restrict__ b_hh)
{
    __shared__ __align__(16) float xt[2][K1_TILE][40];
    const int tid = threadIdx.x;
    const int g = (tid < G3) ? tid : (G3 - 1);

    u64 wih[20];
    {
        const float* w = W_ih + g * FIN;
        #pragma unroll
        for (int j = 0; j < 19; j++) wih[j] = pk(w[2 * j], w[2 * j + 1]);
        wih[19] = pk(w[38], 0.0f);
    }
    const float bias = b_ih[g] + ((g < 2 * H) ? b_hh[g] : 0.0f);
    const int p0 = blockIdx.x * K1_PAIRS;

    int fpair[4], fk[4];
    const float* fptr[4];
    bool fok[4];
    #pragma unroll
    for (int s = 0; s < 4; s++) {
        int idx = tid + s * 320;
        int pr = idx / 40, k = idx - pr * 40;
        fpair[s] = pr; fk[s] = k;
        fok[s] = (k < 39);
        const float* src = (k < 13) ? mfcc0 : (k < 26) ? mfcc1 : mfcc2;
        int f = (k < 13) ? k : (k < 26) ? (k - 13) : (k - 26);
        fptr[s] = src + (size_t)(p0 + pr) * 13 + f;
    }

    #pragma unroll
    for (int s = 0; s < 4; s++)
        xt[0][fpair[s]][fk[s]] = fok[s] ? __ldg(fptr[s]) : 0.0f;
    __syncthreads();

    const unsigned xB0 = (unsigned)__cvta_generic_to_shared(&xt[0][0][0]);

    for (int tile = 0; tile < K1_PAIRS / K1_TILE; tile++) {
        if (tile + 1 < K1_PAIRS / K1_TILE) {
            #pragma unroll
            for (int s = 0; s < 4; s++) {
                fptr[s] += K1_TILE * 13;
                xt[(tile + 1) & 1][fpair[s]][fk[s]] = fok[s] ? __ldg(fptr[s]) : 0.0f;
            }
        }
        const unsigned xB = xB0 + (tile & 1) * (K1_TILE * 40 * 4);
        const int pb = p0 + tile * K1_TILE;
        #pragma unroll 2
        for (int pair = 0; pair < K1_TILE; pair += 2) {
            u64 a0 = 0, a1 = 0, c0 = 0, c1 = 0;
            unsigned ad = xB + pair * 160;
            #pragma unroll
            for (int j = 0; j < 10; j++) {
                u64 p, q, p2, q2;
                lds_v2u64(p,  q,  ad + j * 16);
                lds_v2u64(p2, q2, ad + 160 + j * 16);
                fma2(a0, wih[2 * j],     p);
                fma2(a1, wih[2 * j + 1], q);
                fma2(c0, wih[2 * j],     p2);
                fma2(c1, wih[2 * j + 1], q2);
            }
            if (tid < G3) {
                g_gi[(size_t)(pb + pair) * G3 + g]     = hsum2(a0) + hsum2(a1) + bias;
                g_gi[(size_t)(pb + pair + 1) * G3 + g] = hsum2(c0) + hsum2(c1) + bias;
            }
        }
        __syncthreads();
    }
}

// ---------------------------------------------------------------------------
// Kernel 2: persistent recurrent GRU. 128 CTAs x 800 threads (25 warps).
// thread = (h = tid>>3, c = tid&7). Thread computes r,z,n partials for its h
// over K-chunk [c*14, c*14+14), both batches (42 fma2/step).
// SMEM h layout: chunk c in an 80B slot (20 floats): 16B-aligned AND
// bank-conflict-free (base banks (c*20)%32 = {0,20,8,28,16,4,24,12}).
// Same-c lanes across octets read identical addresses -> broadcast.
// Octet reduction: role-aware butterfly (8 SHFL total incl. z-ship).
// Lanes c<2 finalize r/tanh/h-update (batch = c); lanes 2,3 compute z-sigmoid
// in parallel and ship it via bfly(2). h double-buffered -> 1 barrier/step.
// ---------------------------------------------------------------------------
#define CH     14          // used floats per chunk
#define SLOT   80          // chunk slot bytes (20 floats)
#define HPB    640         // bytes per batch (8 slots)
#define BUFB   1280        // bytes per buffer (2 batches)

__global__ void __launch_bounds__(800, 1) gru_rec_kernel(
    const float* __restrict__ len0,
    const float* __restrict__ W_hh, const float* __restrict__ b_hh,
    const float* __restrict__ W_out, const float* __restrict__ b_out,
    float* __restrict__ out)
{
    __shared__ __align__(16) float h_sh[2 * BUFB / 4];   // 2 bufs x 1280B
    __shared__ float feat_sh[2][2 * H];

    const int tid = threadIdx.x;
    const int h   = tid >> 3;          // 0..99
    const int c   = tid & 7;           // K-chunk; roles: c<2 r/n (b=c), c=2,3 z (b=c-2)
    const int b0  = blockIdx.x * 2;
    const int bl  = c & 1;             // this lane's batch for role work

    // zero both h buffers (incl pad floats — pads never written again)
    for (int i = tid; i < 2 * BUFB / 4; i += 800) h_sh[i] = 0.0f;

    // persistent W_hh chunk rows for 3 gates, zero-padded beyond k=100
    const int k0 = c * CH;
    u64 w[3][7];
    #pragma unroll
    for (int i = 0; i < 3; i++) {
        const float* wr = W_hh + (h + i * H) * H;
        #pragma unroll
        for (int j = 0; j < 7; j++) {
            int k = k0 + 2 * j;
            float x0 = (k     < H) ? wr[k]     : 0.0f;
            float x1 = (k + 1 < H) ? wr[k + 1] : 0.0f;
            w[i][j] = pk(x0, x1);
        }
    }

    // gi pointer: c<2 -> &gi[b][h] (reads +0 for r, +200 for n)
    //             c=2,3 -> &gi[b][H+h] (reads +0 for z)
    const float* gp = g_gi;
    float bh2 = 0.0f;
    if (c < 2) {
        gp = g_gi + (size_t)(b0 + bl) * G3 + h;
        bh2 = b_hh[2 * H + h];
    } else if (c < 4) {
        gp = g_gi + (size_t)(b0 + bl) * G3 + H + h;
    }

    // current gi values
    float gA = 0.0f, gB = 0.0f;        // gA: r (c<2) or z (c=2,3); gB: n (c<2)
    if (c < 4) {
        gA = __ldg(gp);
        if (c < 2) gB = __ldg(gp + 2 * H);
    }

    float hprev = 0.0f, hs = 0.0f, hm = -1e30f;

    const unsigned base = (unsigned)__cvta_generic_to_shared(&h_sh[0]);
    unsigned cur = base, nxt = base + BUFB;        // explicit double-buffer swap
    const unsigned adc = (unsigned)(c * SLOT);     // this lane's chunk slot
    // h-writer slot address components (lanes c<2)
    const unsigned woff = (unsigned)((h / CH) * SLOT + (h % CH) * 4 + bl * HPB);

    __syncthreads();

    for (int t = 0; t < T_STEPS; t++) {
        // prefetch gi(t+1)
        float pA = 0.0f, pB = 0.0f;
        if (t + 1 < T_STEPS && c < 4) {
            const float* gq = gp + GSTR;
            pA = __ldg(gq);
            if (c < 2) pB = __ldg(gq + 2 * H);
            gp = gq;
        }

        // partial dots: 3 gates x 2 batches
        u64 ar0 = 0, az0 = 0, an0 = 0, ar1 = 0, az1 = 0, an1 = 0;
        {
            const unsigned a0 = cur + adc;          // batch 0 chunk slot
            u64 q0, q1, q2, q3, q4, q5, q6;
            lds_v2u64(q0, q1, a0);      lds_v2u64(q2, q3, a0 + 16);
            lds_v2u64(q4, q5, a0 + 32); lds_u64(q6, a0 + 48);
            fma2(ar0, w[0][0], q0); fma2(az0, w[1][0], q0); fma2(an0, w[2][0], q0);
            fma2(ar0, w[0][1], q1); fma2(az0, w[1][1], q1); fma2(an0, w[2][1], q1);
            fma2(ar0, w[0][2], q2); fma2(az0, w[1][2], q2); fma2(an0, w[2][2], q2);
            fma2(ar0, w[0][3], q3); fma2(az0, w[1][3], q3); fma2(an0, w[2][3], q3);
            fma2(ar0, w[0][4], q4); fma2(az0, w[1][4], q4); fma2(an0, w[2][4], q4);
            fma2(ar0, w[0][5], q5); fma2(az0, w[1][5], q5); fma2(an0, w[2][5], q5);
            fma2(ar0, w[0][6], q6); fma2(az0, w[1][6], q6); fma2(an0, w[2][6], q6);
        }
        {
            const unsigned a1 = cur + adc + HPB;    // batch 1 chunk slot
            u64 r0, r1, r2, r3, r4, r5, r6;
            lds_v2u64(r0, r1, a1);      lds_v2u64(r2, r3, a1 + 16);
            lds_v2u64(r4, r5, a1 + 32); lds_u64(r6, a1 + 48);
            fma2(ar1, w[0][0], r0); fma2(az1, w[1][0], r0); fma2(an1, w[2][0], r0);
            fma2(ar1, w[0][1], r1); fma2(az1, w[1][1], r1); fma2(an1, w[2][1], r1);
            fma2(ar1, w[0][2], r2); fma2(az1, w[1][2], r2); fma2(an1, w[2][2], r2);
            fma2(ar1, w[0][3], r3); fma2(az1, w[1][3], r3); fma2(an1, w[2][3], r3);
            fma2(ar1, w[0][4], r4); fma2(az1, w[1][4], r4); fma2(an1, w[2][4], r4);
            fma2(ar1, w[0][5], r5); fma2(az1, w[1][5], r5); fma2(an1, w[2][5], r5);
            fma2(ar1, w[0][6], r6); fma2(az1, w[1][6], r6); fma2(an1, w[2][6], r6);
        }

        float r0s = hsum2(ar0), z0s = hsum2(az0), n0s = hsum2(an0);
        float r1s = hsum2(ar1), z1s = hsum2(az1), n1s = hsum2(an1);

        // ---- role-aware octet butterfly (8 SHFL incl z-ship) ----
        // Round 1 (xor 1): keep own batch bl, receive partner's partial of bl
        float rr = bl ? r1s : r0s;
        float zz = bl ? z1s : z0s;
        float nn = bl ? n1s : n0s;
        rr += __shfl_xor_sync(0xFFFFFFFFu, bl ? r0s : r1s, 1);
        zz += __shfl_xor_sync(0xFFFFFFFFu, bl ? z0s : z1s, 1);
        nn += __shfl_xor_sync(0xFFFFFFFFu, bl ? n0s : n1s, 1);
        // Round 2 (xor 2): lanes c&2 own z (send r), others own r/n (send z)
        {
            float g2 = __shfl_xor_sync(0xFFFFFFFFu, (c & 2) ? rr : zz, 2);
            if (c & 2) zz += g2; else rr += g2;
            nn += __shfl_xor_sync(0xFFFFFFFFu, nn, 2);   // valid on c&2==0 lanes
        }
        // Round 3 (xor 4): same role split
        {
            float g3 = __shfl_xor_sync(0xFFFFFFFFu, (c & 2) ? zz : rr, 4);
            if (c & 2) zz += g3; else rr += g3;
            nn += __shfl_xor_sync(0xFFFFFFFFu, nn, 4);
        }
        // lanes 0,1: rr = Sr, nn = Sn (own batch); lanes 2,3: zz = Sz (own batch)

        // parallel sigmoid: r on lanes 0,1; z on lanes 2,3
        float sig = sigf(gA + ((c & 2) ? zz : rr));
        float zx = __shfl_xor_sync(0xFFFFFFFFu, sig, 2);  // lane bl <- z from lane 2+bl

        if (c < 2) {
            float n  = tanh_acc(gB + sig * (nn + bh2));
            float hn = n + zx * (hprev - n);
            hprev = hn;
            hs += hn;
            hm = fmaxf(hm, hn);
            // store to NEXT buffer
            asm volatile("st.shared.f32 [%0], %1;" :: "r"(nxt + woff), "f"(hprev));
        }
        gA = pA; gB = pB;
        { unsigned tmp = cur; cur = nxt; nxt = tmp; }
        __syncthreads();
    }

    // pooling features
    if (c < 2) {
        float inv = 1.0f / len0[b0 + bl];
        feat_sh[bl][h]     = hs * inv;
        feat_sh[bl][H + h] = hm;
    }
    __syncthreads();

    // output linear: [2 x 20] = feat[2 x 200] @ W_out^T + b_out
    if (tid < 2 * NCLS) {
        int bb = tid / NCLS, cc = tid % NCLS;
        const float* wr = W_out + cc * 2 * H;
        float acc = b_out[cc];
        #pragma unroll 4
        for (int j = 0; j < 2 * H; j++) acc += feat_sh[bb][j] * wr[j];
        out[(b0 + bb) * NCLS + cc] = acc;
    }
}

extern "C" void kernel_launch(void* const* d_in, const int* in_sizes, int n_in,
                              void* d_out, int out_size)
{
    const float* mfcc0 = (const float*)d_in[0];
    const float* mfcc1 = (const float*)d_in[1];
    const float* mfcc2 = (const float*)d_in[2];
    const float* len0  = (const float*)d_in[3];
    const float* W_ih  = (const float*)d_in[4];
    const float* W_hh  = (const float*)d_in[5];
    const float* b_ih  = (const float*)d_in[6];
    const float* b_hh  = (const float*)d_in[7];
    const float* W_out = (const float*)d_in[8];
    const float* b_out = (const float*)d_in[9];
    float* out = (float*)d_out;

    gi_precompute_kernel<<<(T_STEPS * B_TOT) / K1_PAIRS, 320>>>(
        mfcc0, mfcc1, mfcc2, W_ih, b_ih, b_hh);
    gru_rec_kernel<<<B_TOT / 2, 800>>>(len0, W_hh, b_hh, W_out, b_out, out);
}